// round 6
// baseline (speedup 1.0000x reference)
#include <cuda_runtime.h>
#include <cuda_bf16.h>
#include <cstdint>

#define NN 50000
#define NR 32
#define DD 64
#define NE_MAX 1600000
#define TILE 256
#define PADMAX (NR * TILE)
#define SA 72          // As row stride (u32): 72 % 32 == 8 -> LDS.64 frags conflict-free
#define SW 132         // Wp row stride (u32): 132 % 32 == 4 -> LDS.128 frags conflict-free

// Relation-sorted edge arrays (+ per-bucket padding to TILE, norm=0)
__device__ int   g_srcS[NE_MAX + PADMAX];
__device__ int   g_dstS[NE_MAX + PADMAX];
__device__ float g_normS[NE_MAX + PADMAX];
__device__ int   g_binCount[NR];
__device__ int   g_cursor[NR];
__device__ int   g_tileRel[NE_MAX / TILE + NR + 2];
__device__ int   g_numTiles;

__device__ __forceinline__ uint32_t f2tf32(float f) {
    uint32_t r;
    asm("cvt.rna.tf32.f32 %0, %1;" : "=r"(r) : "f"(f));
    return r;
}
__device__ __forceinline__ void mma_tf32(float* c, const uint32_t* a, const uint32_t* b) {
    asm volatile(
        "mma.sync.aligned.m16n8k8.row.col.f32.tf32.tf32.f32 "
        "{%0,%1,%2,%3}, {%4,%5,%6,%7}, {%8,%9}, {%0,%1,%2,%3};"
        : "+f"(c[0]), "+f"(c[1]), "+f"(c[2]), "+f"(c[3])
        : "r"(a[0]), "r"(a[1]), "r"(a[2]), "r"(a[3]), "r"(b[0]), "r"(b[1]));
}

// ---------------------------------------------------------------------------
// Sort pass 1: per-relation histogram.
// ---------------------------------------------------------------------------
__global__ void k_hist(const int* __restrict__ rel, int n) {
    __shared__ int sh[NR];
    if (threadIdx.x < NR) sh[threadIdx.x] = 0;
    __syncthreads();
    for (int i = blockIdx.x * blockDim.x + threadIdx.x; i < n;
         i += gridDim.x * blockDim.x)
        atomicAdd(&sh[__ldg(rel + i)], 1);
    __syncthreads();
    if (threadIdx.x < NR) atomicAdd(&g_binCount[threadIdx.x], sh[threadIdx.x]);
}

// ---------------------------------------------------------------------------
// Sort pass 2: TILE-aligned prefix, tile->rel map, and in-kernel pad zeroing
// (replaces 19MB of scratch memsets). Launch with 32 threads.
// ---------------------------------------------------------------------------
__global__ void k_prefix() {
    int r = threadIdx.x;
    int cnt = g_binCount[r];
    int tiles = (cnt + TILE - 1) / TILE;
    int t = tiles;
#pragma unroll
    for (int d = 1; d < 32; d <<= 1) {
        int v = __shfl_up_sync(0xFFFFFFFFu, t, d);
        if (r >= d) t += v;
    }
    int tileBase = t - tiles;
    int base = tileBase * TILE;
    g_cursor[r] = base;
    for (int i = 0; i < tiles; i++) g_tileRel[tileBase + i] = r;
    for (int i = base + cnt; i < base + tiles * TILE; i++) {
        g_srcS[i] = 0; g_dstS[i] = 0; g_normS[i] = 0.0f;
    }
    if (r == 31) g_numTiles = t;
}

// ---------------------------------------------------------------------------
// Sort pass 3: scatter edges into relation buckets.
// ---------------------------------------------------------------------------
__global__ void __launch_bounds__(256) k_scatter(const int* __restrict__ src,
                                                 const int* __restrict__ dst,
                                                 const int* __restrict__ rel,
                                                 const float* __restrict__ norm,
                                                 int n) {
    __shared__ int sh_cnt[NR], sh_base[NR], sh_pos[NR];
    const int tid = threadIdx.x;
    if (tid < NR) { sh_cnt[tid] = 0; sh_pos[tid] = 0; }
    __syncthreads();
    const int i = blockIdx.x * 256 + tid;
    int r = 0, s = 0, d = 0;
    float nm = 0.0f;
    const bool ok = i < n;
    if (ok) {
        r = __ldg(rel + i); s = __ldg(src + i);
        d = __ldg(dst + i); nm = __ldg(norm + i);
        atomicAdd(&sh_cnt[r], 1);
    }
    __syncthreads();
    if (tid < NR && sh_cnt[tid] > 0)
        sh_base[tid] = atomicAdd(&g_cursor[tid], sh_cnt[tid]);
    __syncthreads();
    if (ok) {
        int pos = sh_base[r] + atomicAdd(&sh_pos[r], 1);
        g_srcS[pos] = s; g_dstS[pos] = d; g_normS[pos] = nm;
    }
}

// ---------------------------------------------------------------------------
// Fused kernel: one 256-edge tile per block (relation fixed per tile).
// 4 warps; warp tile = 64 rows x 64 outs (mt=4, nt=8), K = 8 steps of 8.
// A: k-paired smem layout -> LDS.64 fragments (conflict-free, stride 72).
// B: k-paired + o-permuted -> LDS.128 fragments (conflict-free, stride 132).
// Smem u32: Wp[32*132] | As[256*72] | dst[256] | norm[256]  (~90.5 KB)
// ---------------------------------------------------------------------------
__global__ void __launch_bounds__(128) rgcn_fused(const float* __restrict__ h,
                                                  const float* __restrict__ W,
                                                  float* __restrict__ out) {
    extern __shared__ uint32_t smem[];
    uint32_t* Wp     = smem;                      // 32 rows x 132
    uint32_t* As     = smem + 32 * SW;            // 256 rows x 72
    int*      s_dst  = (int*)(As + 256 * SA);     // 256
    float*    s_norm = (float*)(s_dst + 256);     // 256

    const int tile = blockIdx.x;
    if (tile >= g_numTiles) return;
    const int r    = g_tileRel[tile];
    const int row0 = tile * TILE;

    const int tid = threadIdx.x, wid = tid >> 5, lane = tid & 31;
    const int g = lane >> 2, tg = lane & 3;

    s_dst[tid]        = g_dstS[row0 + tid];
    s_dst[tid + 128]  = g_dstS[row0 + tid + 128];
    s_norm[tid]       = g_normS[row0 + tid];
    s_norm[tid + 128] = g_normS[row0 + tid + 128];

    // --- Stage W_r: element W[k][o] -> Wp[(k>>3)*4+(k&3)][perm(o)*2 + ((k>>2)&1)]
    //     perm(o) = (o&7)*8 + (o>>3)  (so per-thread nt-walk is contiguous)
    {
        const float4* Wr = (const float4*)(W + (size_t)r * DD * DD);
#pragma unroll
        for (int j = 0; j < 8; j++) {
            const int idx4 = tid + j * 128;
            const float4 w4 = __ldg(Wr + idx4);
            const int k = idx4 >> 4, o0 = (idx4 & 15) * 4;
            const int kp = (k >> 3) * 4 + (k & 3), half = (k >> 2) & 1;
            const float wv[4] = {w4.x, w4.y, w4.z, w4.w};
#pragma unroll
            for (int i = 0; i < 4; i++) {
                const int o = o0 + i;
                const int col = ((o & 7) << 3) + (o >> 3);
                Wp[kp * SW + col * 2 + half] = f2tf32(wv[i]);
            }
        }
    }

    // --- Stage A: gather 256 h rows, 8 threads/row, 32B/thread.
    //     k-pair permute within the 8-u32 segment; rotated write order makes
    //     every STS step bank-conflict-free.
    {
        const int arow = tid >> 3, c = tid & 7;
        const int rot = (arow & 3) + ((c >> 2) << 2);   // distinct within bank group
#pragma unroll
        for (int p = 0; p < 16; p++) {
            const int row = p * 16 + arow;
            const int s = g_srcS[row0 + row];
            const float4* hp = (const float4*)(h + (size_t)s * DD + c * 8);
            const float4 v0 = __ldg(hp), v1 = __ldg(hp + 1);
            const float f[8] = {v0.x, v0.y, v0.z, v0.w, v1.x, v1.y, v1.z, v1.w};
            uint32_t q[8];
#pragma unroll
            for (int t = 0; t < 8; t++)
                q[(t & 3) * 2 + (t >> 2)] = f2tf32(f[t]);   // slot = kpair perm
            uint32_t* base = &As[row * SA + c * 8];
#pragma unroll
            for (int s8 = 0; s8 < 8; s8++) {
                const int j = (s8 + rot) & 7;
                base[j] = q[j];
            }
        }
    }
    __syncthreads();

    // --- Compute: warp tile 64x64 ---
    float acc[4][8][4];
#pragma unroll
    for (int mt = 0; mt < 4; mt++)
#pragma unroll
        for (int nt = 0; nt < 8; nt++)
#pragma unroll
            for (int q = 0; q < 4; q++) acc[mt][nt][q] = 0.0f;

    const int wrow = wid * 64;
#pragma unroll
    for (int ks = 0; ks < 8; ks++) {
        uint32_t a[4][4];
#pragma unroll
        for (int mt = 0; mt < 4; mt++) {
            const int r0 = wrow + mt * 16 + g;
            const uint2 p0 = *(const uint2*)&As[r0 * SA + ks * 8 + tg * 2];
            const uint2 p1 = *(const uint2*)&As[(r0 + 8) * SA + ks * 8 + tg * 2];
            a[mt][0] = p0.x; a[mt][1] = p1.x; a[mt][2] = p0.y; a[mt][3] = p1.y;
        }
        uint32_t b[8][2];
        const uint32_t* brow = &Wp[(ks * 4 + tg) * SW + g * 16];
#pragma unroll
        for (int m = 0; m < 4; m++) {
            const uint4 bb = *(const uint4*)(brow + m * 4);
            b[2 * m][0]     = bb.x; b[2 * m][1]     = bb.y;
            b[2 * m + 1][0] = bb.z; b[2 * m + 1][1] = bb.w;
        }
#pragma unroll
        for (int mt = 0; mt < 4; mt++)
#pragma unroll
            for (int nt = 0; nt < 8; nt++)
                mma_tf32(acc[mt][nt], a[mt], b[nt]);
    }

    // --- Epilogue: scale by norm, red.v2 into out[dst] ---
#pragma unroll
    for (int mt = 0; mt < 4; mt++) {
        const int lr0 = wrow + mt * 16 + g, lr1 = lr0 + 8;
        const float n0 = s_norm[lr0], n1 = s_norm[lr1];
        float* o0 = out + (size_t)s_dst[lr0] * DD;
        float* o1 = out + (size_t)s_dst[lr1] * DD;
#pragma unroll
        for (int nt = 0; nt < 8; nt++) {
            const int oc = nt * 8 + 2 * tg;
            asm volatile("red.global.add.v2.f32 [%0], {%1, %2};"
                         :: "l"(o0 + oc), "f"(acc[mt][nt][0] * n0),
                            "f"(acc[mt][nt][1] * n0) : "memory");
            asm volatile("red.global.add.v2.f32 [%0], {%1, %2};"
                         :: "l"(o1 + oc), "f"(acc[mt][nt][2] * n1),
                            "f"(acc[mt][nt][3] * n1) : "memory");
        }
    }
}

// ---------------------------------------------------------------------------
extern "C" void kernel_launch(void* const* d_in, const int* in_sizes, int n_in,
                              void* d_out, int out_size) {
    const float* h    = (const float*)d_in[0];
    const float* W    = (const float*)d_in[1];
    const int*   src  = (const int*)d_in[2];
    const int*   dst  = (const int*)d_in[3];
    const int*   rel  = (const int*)d_in[4];
    const float* norm = (const float*)d_in[5];
    float*       out  = (float*)d_out;

    const int n_edges = in_sizes[2];   // 1600000

    void* p_cnt;
    cudaGetSymbolAddress(&p_cnt, g_binCount);
    cudaMemsetAsync(out,   0, (size_t)out_size * sizeof(float), 0);
    cudaMemsetAsync(p_cnt, 0, sizeof(int) * NR, 0);

    k_hist<<<592, 256>>>(rel, n_edges);
    k_prefix<<<1, 32>>>();
    k_scatter<<<(n_edges + 255) / 256, 256>>>(src, dst, rel, norm, n_edges);

    const int smem_bytes = (32 * SW + 256 * SA + 256 + 256) * 4;
    static bool attr_set = false;
    if (!attr_set) {
        cudaFuncSetAttribute(rgcn_fused,
                             cudaFuncAttributeMaxDynamicSharedMemorySize,
                             smem_bytes);
        attr_set = true;
    }
    const int max_tiles = n_edges / TILE + NR + 1;
    rgcn_fused<<<max_tiles, 128, smem_bytes>>>(h, W, out);
}

// round 7
// speedup vs baseline: 1.0300x; 1.0300x over previous
#include <cuda_runtime.h>
#include <cuda_bf16.h>
#include <cstdint>

#define NN 50000
#define NR 32
#define DD 64
#define NE_MAX 1600000
#define TILE 128
#define PADMAX (NR * TILE)
#define SA 72          // As row stride (u32): LDS.64 fragments conflict-free
#define FUSED_GRID 296 // ~2 blocks/SM on 148 SMs

// Relation-sorted edge arrays (+ per-bucket padding to TILE, norm=0)
__device__ int   g_srcS[NE_MAX + PADMAX];
__device__ int   g_dstS[NE_MAX + PADMAX];
__device__ float g_normS[NE_MAX + PADMAX];
__device__ int   g_binCount[NR];
__device__ int   g_cursor[NR];
__device__ int   g_tileRel[NE_MAX / TILE + NR + 2];
__device__ int   g_numTiles;

__device__ __forceinline__ uint32_t f2tf32(float f) {
    uint32_t r;
    asm("cvt.rna.tf32.f32 %0, %1;" : "=r"(r) : "f"(f));
    return r;
}
__device__ __forceinline__ void mma_tf32(float* c, const uint32_t* a, const uint32_t* b) {
    asm volatile(
        "mma.sync.aligned.m16n8k8.row.col.f32.tf32.tf32.f32 "
        "{%0,%1,%2,%3}, {%4,%5,%6,%7}, {%8,%9}, {%0,%1,%2,%3};"
        : "+f"(c[0]), "+f"(c[1]), "+f"(c[2]), "+f"(c[3])
        : "r"(a[0]), "r"(a[1]), "r"(a[2]), "r"(a[3]), "r"(b[0]), "r"(b[1]));
}

// ---------------------------------------------------------------------------
// Sort pass 1: per-relation histogram.
// ---------------------------------------------------------------------------
__global__ void k_hist(const int* __restrict__ rel, int n) {
    __shared__ int sh[NR];
    if (threadIdx.x < NR) sh[threadIdx.x] = 0;
    __syncthreads();
    for (int i = blockIdx.x * blockDim.x + threadIdx.x; i < n;
         i += gridDim.x * blockDim.x)
        atomicAdd(&sh[__ldg(rel + i)], 1);
    __syncthreads();
    if (threadIdx.x < NR) atomicAdd(&g_binCount[threadIdx.x], sh[threadIdx.x]);
}

// ---------------------------------------------------------------------------
// Sort pass 2: TILE-aligned prefix, tile->rel map, in-kernel pad zeroing.
// Launch with 32 threads.
// ---------------------------------------------------------------------------
__global__ void k_prefix() {
    int r = threadIdx.x;
    int cnt = g_binCount[r];
    int tiles = (cnt + TILE - 1) / TILE;
    int t = tiles;
#pragma unroll
    for (int d = 1; d < 32; d <<= 1) {
        int v = __shfl_up_sync(0xFFFFFFFFu, t, d);
        if (r >= d) t += v;
    }
    int tileBase = t - tiles;
    int base = tileBase * TILE;
    g_cursor[r] = base;
    for (int i = 0; i < tiles; i++) g_tileRel[tileBase + i] = r;
    for (int i = base + cnt; i < base + tiles * TILE; i++) {
        g_srcS[i] = 0; g_dstS[i] = 0; g_normS[i] = 0.0f;
    }
    if (r == 31) g_numTiles = t;
}

// ---------------------------------------------------------------------------
// Sort pass 3: scatter edges into relation buckets.
// ---------------------------------------------------------------------------
__global__ void __launch_bounds__(256) k_scatter(const int* __restrict__ src,
                                                 const int* __restrict__ dst,
                                                 const int* __restrict__ rel,
                                                 const float* __restrict__ norm,
                                                 int n) {
    __shared__ int sh_cnt[NR], sh_base[NR], sh_pos[NR];
    const int tid = threadIdx.x;
    if (tid < NR) { sh_cnt[tid] = 0; sh_pos[tid] = 0; }
    __syncthreads();
    const int i = blockIdx.x * 256 + tid;
    int r = 0, s = 0, d = 0;
    float nm = 0.0f;
    const bool ok = i < n;
    if (ok) {
        r = __ldg(rel + i); s = __ldg(src + i);
        d = __ldg(dst + i); nm = __ldg(norm + i);
        atomicAdd(&sh_cnt[r], 1);
    }
    __syncthreads();
    if (tid < NR && sh_cnt[tid] > 0)
        sh_base[tid] = atomicAdd(&g_cursor[tid], sh_cnt[tid]);
    __syncthreads();
    if (ok) {
        int pos = sh_base[r] + atomicAdd(&sh_pos[r], 1);
        g_srcS[pos] = s; g_dstS[pos] = d; g_normS[pos] = nm;
    }
}

// ---------------------------------------------------------------------------
// Fused persistent kernel. Each block walks a CONTIGUOUS run of 128-edge
// tiles (sorted by relation). B fragments for the current relation live in
// 128 registers per thread, restaged from global W only on relation change.
// Per tile: gather h[src] -> smem (k-paired, conflict-free), 8x(LDS.64 x4 +
// 16 HMMA), norm-scale + red.global.add.v2 into out[dst].
// Smem u32: As[128*72] | dst[128] | norm[128]  (~38 KB)
// ---------------------------------------------------------------------------
__global__ void __launch_bounds__(128) rgcn_fused(const float* __restrict__ h,
                                                  const float* __restrict__ W,
                                                  float* __restrict__ out) {
    extern __shared__ uint32_t smem[];
    uint32_t* As     = smem;                      // 128 x 72
    int*      s_dst  = (int*)(As + TILE * SA);    // 128
    float*    s_norm = (float*)(s_dst + TILE);    // 128

    const int nT = g_numTiles;
    const int chunk = (nT + (int)gridDim.x - 1) / (int)gridDim.x;
    int t0 = blockIdx.x * chunk;
    int t1 = t0 + chunk; if (t1 > nT) t1 = nT;
    if (t0 >= nT) return;

    const int tid = threadIdx.x, wid = tid >> 5, lane = tid & 31;
    const int g = lane >> 2, tg = lane & 3;
    const int arow = tid >> 3, c = tid & 7;
    const int rot  = (arow & 3) + ((c >> 2) << 2);
    const int wrow = wid * 32;

    uint32_t breg[8][8][2];   // [ks][nt][2] — statically indexed everywhere
    int rCur = -1;

    for (int tile = t0; tile < t1; tile++) {
        const int r = g_tileRel[tile];
        if (r != rCur) {
            rCur = r;
            const float* Wr = W + (size_t)r * DD * DD;
#pragma unroll
            for (int ks = 0; ks < 8; ks++)
#pragma unroll
                for (int nt = 0; nt < 8; nt++) {
                    breg[ks][nt][0] =
                        f2tf32(__ldg(Wr + (ks * 8 + tg) * DD + nt * 8 + g));
                    breg[ks][nt][1] =
                        f2tf32(__ldg(Wr + (ks * 8 + tg + 4) * DD + nt * 8 + g));
                }
        }

        const int row0 = tile * TILE;
        s_dst[tid]  = g_dstS[row0 + tid];
        s_norm[tid] = g_normS[row0 + tid];

        // Gather A: 8 threads/row, 32B per thread; k-pair permuted slots,
        // rotated write order => every STS step bank-conflict-free.
#pragma unroll
        for (int p = 0; p < 8; p++) {
            const int row = p * 16 + arow;
            const int s = g_srcS[row0 + row];
            const float4* hp = (const float4*)(h + (size_t)s * DD + c * 8);
            const float4 v0 = __ldg(hp), v1 = __ldg(hp + 1);
            const float f[8] = {v0.x, v0.y, v0.z, v0.w, v1.x, v1.y, v1.z, v1.w};
            uint32_t q[8];
#pragma unroll
            for (int t = 0; t < 8; t++)
                q[(t & 3) * 2 + (t >> 2)] = f2tf32(f[t]);
            uint32_t* base = &As[row * SA + c * 8];
#pragma unroll
            for (int s8 = 0; s8 < 8; s8++) {
                const int j = (s8 + rot) & 7;
                base[j] = q[j];
            }
        }
        __syncthreads();

        // Compute: warp tile 32 x 64.
        float acc[2][8][4];
#pragma unroll
        for (int mt = 0; mt < 2; mt++)
#pragma unroll
            for (int nt = 0; nt < 8; nt++)
#pragma unroll
                for (int q = 0; q < 4; q++) acc[mt][nt][q] = 0.0f;

#pragma unroll
        for (int ks = 0; ks < 8; ks++) {
            uint32_t a[2][4];
#pragma unroll
            for (int mt = 0; mt < 2; mt++) {
                const int r0 = wrow + mt * 16 + g;
                const uint2 p0 = *(const uint2*)&As[r0 * SA + ks * 8 + tg * 2];
                const uint2 p1 = *(const uint2*)&As[(r0 + 8) * SA + ks * 8 + tg * 2];
                a[mt][0] = p0.x; a[mt][1] = p1.x; a[mt][2] = p0.y; a[mt][3] = p1.y;
            }
#pragma unroll
            for (int mt = 0; mt < 2; mt++)
#pragma unroll
                for (int nt = 0; nt < 8; nt++)
                    mma_tf32(acc[mt][nt], a[mt], breg[ks][nt]);
        }

        // Epilogue: scale by norm, red.v2 into out[dst].
#pragma unroll
        for (int mt = 0; mt < 2; mt++) {
            const int lr0 = wrow + mt * 16 + g, lr1 = lr0 + 8;
            const float n0 = s_norm[lr0], n1 = s_norm[lr1];
            float* o0 = out + (size_t)s_dst[lr0] * DD;
            float* o1 = out + (size_t)s_dst[lr1] * DD;
#pragma unroll
            for (int nt = 0; nt < 8; nt++) {
                const int oc = nt * 8 + 2 * tg;
                asm volatile("red.global.add.v2.f32 [%0], {%1, %2};"
                             :: "l"(o0 + oc), "f"(acc[mt][nt][0] * n0),
                                "f"(acc[mt][nt][1] * n0) : "memory");
                asm volatile("red.global.add.v2.f32 [%0], {%1, %2};"
                             :: "l"(o1 + oc), "f"(acc[mt][nt][2] * n1),
                                "f"(acc[mt][nt][3] * n1) : "memory");
            }
        }
        __syncthreads();   // As/s_dst/s_norm consumed before next tile's stage
    }
}

// ---------------------------------------------------------------------------
extern "C" void kernel_launch(void* const* d_in, const int* in_sizes, int n_in,
                              void* d_out, int out_size) {
    const float* h    = (const float*)d_in[0];
    const float* W    = (const float*)d_in[1];
    const int*   src  = (const int*)d_in[2];
    const int*   dst  = (const int*)d_in[3];
    const int*   rel  = (const int*)d_in[4];
    const float* norm = (const float*)d_in[5];
    float*       out  = (float*)d_out;

    const int n_edges = in_sizes[2];   // 1600000

    void* p_cnt;
    cudaGetSymbolAddress(&p_cnt, g_binCount);
    cudaMemsetAsync(out,   0, (size_t)out_size * sizeof(float), 0);
    cudaMemsetAsync(p_cnt, 0, sizeof(int) * NR, 0);

    k_hist<<<592, 256>>>(rel, n_edges);
    k_prefix<<<1, 32>>>();
    k_scatter<<<(n_edges + 255) / 256, 256>>>(src, dst, rel, norm, n_edges);

    const int smem_bytes = (TILE * SA + TILE + TILE) * 4;
    static bool attr_set = false;
    if (!attr_set) {
        cudaFuncSetAttribute(rgcn_fused,
                             cudaFuncAttributeMaxDynamicSharedMemorySize,
                             smem_bytes);
        attr_set = true;
    }
    rgcn_fused<<<FUSED_GRID, 128, smem_bytes>>>(h, W, out);
}